// round 2
// baseline (speedup 1.0000x reference)
#include <cuda_runtime.h>
#include <math_constants.h>
#include <cstdint>

#define EPS 1e-5f

// ---------------- scratch (static device globals; no allocation) ----------------
// B=8, C=256, C2=128, H=W=64, HW=4096, pooled HW=1024
__device__ float g_x1[8 * 128 * 4096];    // conv1 output, NCHW flat == X1 [4096,128] rm per batch
__device__ float g_y2[8 * 128 * 4096];    // conv2 output pre-pool
__device__ float g_x23[8 * 128 * 1024];   // pooled; == X2 [128,1024] and X3 [1024,128] views
__device__ float g_attn[8 * 128 * 4096];  // attention out [4096,128] rm == NCHW for conv3

// ---------------- 1x1 conv + BN + ReLU (+ optional residual) as tiled GEMM ----------------
__global__ __launch_bounds__(256) void conv_bn_relu_kernel(
    const float* __restrict__ X, const float* __restrict__ W,
    const float* __restrict__ bias, const float* __restrict__ gam,
    const float* __restrict__ beta, const float* __restrict__ mean,
    const float* __restrict__ var, const float* __restrict__ resid,
    float* __restrict__ Y, int K, int O, int HW)
{
    __shared__ float Ws[16][65];
    __shared__ float Xs[16][64];

    const int b  = blockIdx.z;
    const int o0 = blockIdx.y * 64;
    const int p0 = blockIdx.x * 64;
    const int tid = threadIdx.x;
    const int tx = tid & 15, ty = tid >> 4;

    const float* Xb = X + (size_t)b * K * HW;

    float acc[4][4];
#pragma unroll
    for (int i = 0; i < 4; i++)
#pragma unroll
        for (int j = 0; j < 4; j++) acc[i][j] = 0.f;

    for (int k0 = 0; k0 < K; k0 += 16) {
        {
            int kk = tid & 15, i = tid >> 4;
#pragma unroll
            for (int l = 0; l < 4; l++)
                Ws[kk][i + 16 * l] = W[(size_t)(o0 + i + 16 * l) * K + (k0 + kk)];
        }
        {
            int pp = tid & 63, kb = tid >> 6;
#pragma unroll
            for (int l = 0; l < 4; l++)
                Xs[kb + 4 * l][pp] = Xb[(size_t)(k0 + kb + 4 * l) * HW + (p0 + pp)];
        }
        __syncthreads();
#pragma unroll
        for (int kk = 0; kk < 16; kk++) {
            float a0 = Ws[kk][ty * 4 + 0];
            float a1 = Ws[kk][ty * 4 + 1];
            float a2 = Ws[kk][ty * 4 + 2];
            float a3 = Ws[kk][ty * 4 + 3];
            float4 bv = *(const float4*)&Xs[kk][tx * 4];
            acc[0][0] += a0 * bv.x; acc[0][1] += a0 * bv.y; acc[0][2] += a0 * bv.z; acc[0][3] += a0 * bv.w;
            acc[1][0] += a1 * bv.x; acc[1][1] += a1 * bv.y; acc[1][2] += a1 * bv.z; acc[1][3] += a1 * bv.w;
            acc[2][0] += a2 * bv.x; acc[2][1] += a2 * bv.y; acc[2][2] += a2 * bv.z; acc[2][3] += a2 * bv.w;
            acc[3][0] += a3 * bv.x; acc[3][1] += a3 * bv.y; acc[3][2] += a3 * bv.z; acc[3][3] += a3 * bv.w;
        }
        __syncthreads();
    }

#pragma unroll
    for (int i = 0; i < 4; i++) {
        int o = o0 + ty * 4 + i;
        float s  = gam[o] * rsqrtf(var[o] + EPS);
        float sh = beta[o] - mean[o] * s;
        float bi = bias[o];
        size_t base = (size_t)b * O * HW + (size_t)o * HW + p0 + tx * 4;
#pragma unroll
        for (int j = 0; j < 4; j++) {
            float v = fmaxf((acc[i][j] + bi) * s + sh, 0.f);
            if (resid) v += resid[base + j];
            Y[base + j] = v;
        }
    }
}

// ---------------- maxpool 3x3 stride 2 pad 1 : [B,128,64,64] -> [B,128,32,32] ----------------
__global__ void maxpool_kernel(const float* __restrict__ X, float* __restrict__ Y)
{
    int idx = blockIdx.x * 256 + threadIdx.x;
    if (idx >= 8 * 128 * 1024) return;
    int q = idx & 31, p = (idx >> 5) & 31, c = (idx >> 10) & 127, b = idx >> 17;
    const float* Xp = X + ((size_t)(b * 128 + c)) * 4096;
    int r0 = 2 * p - 1, c0 = 2 * q - 1;
    float m = -CUDART_INF_F;
#pragma unroll
    for (int dr = 0; dr < 3; dr++) {
        int r = r0 + dr;
        if (r < 0 || r >= 64) continue;
#pragma unroll
        for (int dc = 0; dc < 3; dc++) {
            int cc = c0 + dc;
            if (cc < 0 || cc >= 64) continue;
            m = fmaxf(m, Xp[r * 64 + cc]);
        }
    }
    Y[idx] = m;
}

// ---------------- fused attention: out = softmax(X1 @ X2) @ X3 ----------------
// 512 threads: tx = lane (0..31) -> 4 cols each (128 cols), ty = warp (0..15) -> 8 rows each (128 rows)
// Each output row lives entirely inside one warp => broadcast A-loads + full-warp shuffle softmax.
#define PITCH_X1 132
#define ATTN_SMEM_FLOATS (128 * PITCH_X1 + 128 * 128 + 128 * 128)
#define ATTN_SMEM_BYTES  (ATTN_SMEM_FLOATS * 4)

__global__ __launch_bounds__(512, 1) void attn_kernel(
    const float* __restrict__ x1, const float* __restrict__ kv, float* __restrict__ out)
{
    extern __shared__ float sm[];
    float* X1s = sm;                       // [k][i], pitch 132
    float* MPs = sm + 128 * PITCH_X1;      // [128][128]: Ms (X2 chunk) then reused for P
    float* X3s = MPs + 128 * 128;          // [128][128]

    const int b  = blockIdx.y;
    const int i0 = blockIdx.x * 128;
    const int tid = threadIdx.x;
    const int tx = tid & 31;       // lane
    const int ty = tid >> 5;       // warp (row group)

    const float* X1g = x1 + (size_t)b * 524288 + (size_t)i0 * 128;
    const float* Bg  = kv + (size_t)b * 131072;

    // load X1 tile transposed: X1s[k][i]
#pragma unroll
    for (int l = 0; l < 8; l++) {
        int flat = tid + l * 512;           // float4 index over [128 rows][32 f4]
        int i = flat >> 5, kq = flat & 31;
        float4 v = *(const float4*)(X1g + (size_t)i * 128 + kq * 4);
        int k = kq * 4;
        X1s[(k + 0) * PITCH_X1 + i] = v.x;
        X1s[(k + 1) * PITCH_X1 + i] = v.y;
        X1s[(k + 2) * PITCH_X1 + i] = v.z;
        X1s[(k + 3) * PITCH_X1 + i] = v.w;
    }

    float Oacc[8][4];
    float mrow[8], lrow[8];
#pragma unroll
    for (int r = 0; r < 8; r++) {
        mrow[r] = -CUDART_INF_F;
        lrow[r] = 0.f;
#pragma unroll
        for (int c = 0; c < 4; c++) Oacc[r][c] = 0.f;
    }

    for (int j0 = 0; j0 < 1024; j0 += 128) {
        __syncthreads();  // protect MPs/X3s from previous-iteration readers (and X1 stores iter 0)
        // Ms[c][j] = Bg[c*1024 + j0 + j]
#pragma unroll
        for (int l = 0; l < 8; l++) {
            int flat = tid + l * 512;
            int c = flat >> 5, jq = flat & 31;
            *(float4*)&MPs[c * 128 + jq * 4] = *(const float4*)(Bg + (size_t)c * 1024 + j0 + jq * 4);
        }
        // X3s: contiguous block Bg[j0*128 ..]
        {
            const float4* src = (const float4*)(Bg + (size_t)j0 * 128);
#pragma unroll
            for (int l = 0; l < 8; l++)
                ((float4*)X3s)[tid + l * 512] = src[tid + l * 512];
        }
        __syncthreads();

        // gemm1: S[i][j] = sum_k X1s[k][i] * Ms[k][j]
        float S[8][4];
#pragma unroll
        for (int r = 0; r < 8; r++)
#pragma unroll
            for (int c = 0; c < 4; c++) S[r][c] = 0.f;

#pragma unroll 4
        for (int k = 0; k < 128; k++) {
            float4 a0 = *(const float4*)&X1s[k * PITCH_X1 + ty * 8];      // rows ty*8..+3 (broadcast)
            float4 a1 = *(const float4*)&X1s[k * PITCH_X1 + ty * 8 + 4];  // rows +4..+7
            float4 bv = *(const float4*)&MPs[k * 128 + tx * 4];
            S[0][0] += a0.x * bv.x; S[0][1] += a0.x * bv.y; S[0][2] += a0.x * bv.z; S[0][3] += a0.x * bv.w;
            S[1][0] += a0.y * bv.x; S[1][1] += a0.y * bv.y; S[1][2] += a0.y * bv.z; S[1][3] += a0.y * bv.w;
            S[2][0] += a0.z * bv.x; S[2][1] += a0.z * bv.y; S[2][2] += a0.z * bv.z; S[2][3] += a0.z * bv.w;
            S[3][0] += a0.w * bv.x; S[3][1] += a0.w * bv.y; S[3][2] += a0.w * bv.z; S[3][3] += a0.w * bv.w;
            S[4][0] += a1.x * bv.x; S[4][1] += a1.x * bv.y; S[4][2] += a1.x * bv.z; S[4][3] += a1.x * bv.w;
            S[5][0] += a1.y * bv.x; S[5][1] += a1.y * bv.y; S[5][2] += a1.y * bv.z; S[5][3] += a1.y * bv.w;
            S[6][0] += a1.z * bv.x; S[6][1] += a1.z * bv.y; S[6][2] += a1.z * bv.z; S[6][3] += a1.z * bv.w;
            S[7][0] += a1.w * bv.x; S[7][1] += a1.w * bv.y; S[7][2] += a1.w * bv.z; S[7][3] += a1.w * bv.w;
        }

        // online softmax: each row fully inside one warp (32 lanes x 4 cols)
#pragma unroll
        for (int r = 0; r < 8; r++) {
            float mx = fmaxf(fmaxf(S[r][0], S[r][1]), fmaxf(S[r][2], S[r][3]));
            mx = fmaxf(mx, __shfl_xor_sync(0xffffffffu, mx, 1));
            mx = fmaxf(mx, __shfl_xor_sync(0xffffffffu, mx, 2));
            mx = fmaxf(mx, __shfl_xor_sync(0xffffffffu, mx, 4));
            mx = fmaxf(mx, __shfl_xor_sync(0xffffffffu, mx, 8));
            mx = fmaxf(mx, __shfl_xor_sync(0xffffffffu, mx, 16));
            float mn = fmaxf(mrow[r], mx);
            float f  = __expf(mrow[r] - mn);   // 0 when mrow was -inf
            mrow[r] = mn;
            float s = 0.f;
#pragma unroll
            for (int c = 0; c < 4; c++) {
                float p = __expf(S[r][c] - mn);
                S[r][c] = p;
                s += p;
            }
            s += __shfl_xor_sync(0xffffffffu, s, 1);
            s += __shfl_xor_sync(0xffffffffu, s, 2);
            s += __shfl_xor_sync(0xffffffffu, s, 4);
            s += __shfl_xor_sync(0xffffffffu, s, 8);
            s += __shfl_xor_sync(0xffffffffu, s, 16);
            lrow[r] = lrow[r] * f + s;
#pragma unroll
            for (int c = 0; c < 4; c++) Oacc[r][c] *= f;
        }

        __syncthreads();  // all warps done reading Ms
        // store P into MPs as [i][j]
#pragma unroll
        for (int r = 0; r < 8; r++)
            *(float4*)&MPs[(ty * 8 + r) * 128 + tx * 4] = make_float4(S[r][0], S[r][1], S[r][2], S[r][3]);
        __syncthreads();

        // gemm2: O[i][c] += sum_j P[i][j] * X3s[j][c], j unrolled by 4 for vector A-loads
#pragma unroll 2
        for (int j4 = 0; j4 < 32; j4++) {
            float4 a4[8];
#pragma unroll
            for (int r = 0; r < 8; r++)
                a4[r] = *(const float4*)&MPs[(ty * 8 + r) * 128 + j4 * 4];   // broadcast
#pragma unroll
            for (int d = 0; d < 4; d++) {
                float4 bv = *(const float4*)&X3s[(j4 * 4 + d) * 128 + tx * 4];
                float av[8] = { ((const float*)&a4[0])[d], ((const float*)&a4[1])[d],
                                ((const float*)&a4[2])[d], ((const float*)&a4[3])[d],
                                ((const float*)&a4[4])[d], ((const float*)&a4[5])[d],
                                ((const float*)&a4[6])[d], ((const float*)&a4[7])[d] };
#pragma unroll
                for (int r = 0; r < 8; r++) {
                    Oacc[r][0] += av[r] * bv.x; Oacc[r][1] += av[r] * bv.y;
                    Oacc[r][2] += av[r] * bv.z; Oacc[r][3] += av[r] * bv.w;
                }
            }
        }
    }

    float* og = out + (size_t)b * 524288 + (size_t)i0 * 128;
#pragma unroll
    for (int r = 0; r < 8; r++) {
        float inv = 1.0f / lrow[r];
        *(float4*)(og + (size_t)(ty * 8 + r) * 128 + tx * 4) =
            make_float4(Oacc[r][0] * inv, Oacc[r][1] * inv, Oacc[r][2] * inv, Oacc[r][3] * inv);
    }
}

// ---------------- launcher ----------------
extern "C" void kernel_launch(void* const* d_in, const int* in_sizes, int n_in,
                              void* d_out, int out_size)
{
    const float* a       = (const float*)d_in[0];
    const float* conv1_w = (const float*)d_in[1];
    const float* conv1_b = (const float*)d_in[2];
    const float* bn1_g   = (const float*)d_in[3];
    const float* bn1_b   = (const float*)d_in[4];
    const float* bn1_m   = (const float*)d_in[5];
    const float* bn1_v   = (const float*)d_in[6];
    const float* conv2_w = (const float*)d_in[7];
    const float* conv2_b = (const float*)d_in[8];
    const float* bn2_g   = (const float*)d_in[9];
    const float* bn2_b   = (const float*)d_in[10];
    const float* bn2_m   = (const float*)d_in[11];
    const float* bn2_v   = (const float*)d_in[12];
    const float* conv3_w = (const float*)d_in[13];
    const float* conv3_b = (const float*)d_in[14];
    const float* bn3_g   = (const float*)d_in[15];
    const float* bn3_b   = (const float*)d_in[16];
    const float* bn3_m   = (const float*)d_in[17];
    const float* bn3_v   = (const float*)d_in[18];
    float* out = (float*)d_out;

    float *p_x1, *p_y2, *p_x23, *p_attn;
    cudaGetSymbolAddress((void**)&p_x1,   g_x1);
    cudaGetSymbolAddress((void**)&p_y2,   g_y2);
    cudaGetSymbolAddress((void**)&p_x23,  g_x23);
    cudaGetSymbolAddress((void**)&p_attn, g_attn);

    cudaFuncSetAttribute(attn_kernel, cudaFuncAttributeMaxDynamicSharedMemorySize, ATTN_SMEM_BYTES);

    const int HW = 4096;
    dim3 blk(256);

    // conv1: [128,256] x [256,4096] per batch -> g_x1
    conv_bn_relu_kernel<<<dim3(HW / 64, 128 / 64, 8), blk>>>(
        a, conv1_w, conv1_b, bn1_g, bn1_b, bn1_m, bn1_v, nullptr, p_x1, 256, 128, HW);

    // conv2 -> g_y2
    conv_bn_relu_kernel<<<dim3(HW / 64, 128 / 64, 8), blk>>>(
        a, conv2_w, conv2_b, bn2_g, bn2_b, bn2_m, bn2_v, nullptr, p_y2, 256, 128, HW);

    // maxpool -> g_x23
    maxpool_kernel<<<(8 * 128 * 1024) / 256, blk>>>(p_y2, p_x23);

    // attention -> g_attn
    attn_kernel<<<dim3(32, 8), dim3(512), ATTN_SMEM_BYTES>>>(p_x1, p_x23, p_attn);

    // conv3 + residual -> out
    conv_bn_relu_kernel<<<dim3(HW / 64, 256 / 64, 8), blk>>>(
        p_attn, conv3_w, conv3_b, bn3_g, bn3_b, bn3_m, bn3_v, a, out, 128, 256, HW);
}

// round 4
// speedup vs baseline: 1.7535x; 1.7535x over previous
#include <cuda_runtime.h>
#include <cuda_bf16.h>
#include <math_constants.h>
#include <cstdint>

#define EPS 1e-5f

// ---------------- scratch ----------------
__device__ float g_x1[8 * 128 * 4096];
__device__ float g_y2[8 * 128 * 4096];
__device__ float g_x23[8 * 128 * 1024];
__device__ float g_attn[8 * 128 * 4096];
__device__ __nv_bfloat16 g_x2t_hi[8 * 1024 * 128];  // [b][j][c]
__device__ __nv_bfloat16 g_x2t_lo[8 * 1024 * 128];
__device__ __nv_bfloat16 g_x3t_hi[8 * 128 * 1024];  // [b][c][j]
__device__ __nv_bfloat16 g_x3t_lo[8 * 128 * 1024];

// ---------------- helpers ----------------
__device__ __forceinline__ void mma_bf16(float& c0, float& c1, float& c2, float& c3,
                                         uint32_t a0, uint32_t a1, uint32_t a2, uint32_t a3,
                                         uint32_t b0, uint32_t b1)
{
    asm volatile("mma.sync.aligned.m16n8k16.row.col.f32.bf16.bf16.f32 "
                 "{%0,%1,%2,%3}, {%4,%5,%6,%7}, {%8,%9}, {%0,%1,%2,%3};"
                 : "+f"(c0), "+f"(c1), "+f"(c2), "+f"(c3)
                 : "r"(a0), "r"(a1), "r"(a2), "r"(a3), "r"(b0), "r"(b1));
}
// pack (e0 -> low, e1 -> high) as bf16x2; also produce residual pack
__device__ __forceinline__ void split2(float e0, float e1, uint32_t& hi, uint32_t& lo)
{
    asm("cvt.rn.bf16x2.f32 %0, %1, %2;" : "=r"(hi) : "f"(e1), "f"(e0));
    float f0h = __uint_as_float(hi << 16);
    float f1h = __uint_as_float(hi & 0xffff0000u);
    asm("cvt.rn.bf16x2.f32 %0, %1, %2;" : "=r"(lo) : "f"(e1 - f1h), "f"(e0 - f0h));
}

// ---------------- conv 1x1 + BN + ReLU (+resid) ----------------
__global__ __launch_bounds__(256) void conv_bn_relu_kernel(
    const float* __restrict__ X, const float* __restrict__ W,
    const float* __restrict__ bias, const float* __restrict__ gam,
    const float* __restrict__ beta, const float* __restrict__ mean,
    const float* __restrict__ var, const float* __restrict__ resid,
    float* __restrict__ Y, int K, int O, int HW)
{
    __shared__ float Ws[16][65];
    __shared__ float Xs[16][64];
    const int b  = blockIdx.z;
    const int o0 = blockIdx.y * 64;
    const int p0 = blockIdx.x * 64;
    const int tid = threadIdx.x;
    const int tx = tid & 15, ty = tid >> 4;
    const float* Xb = X + (size_t)b * K * HW;

    float acc[4][4];
#pragma unroll
    for (int i = 0; i < 4; i++)
#pragma unroll
        for (int j = 0; j < 4; j++) acc[i][j] = 0.f;

    for (int k0 = 0; k0 < K; k0 += 16) {
        {
            int kk = tid & 15, i = tid >> 4;
#pragma unroll
            for (int l = 0; l < 4; l++)
                Ws[kk][i + 16 * l] = W[(size_t)(o0 + i + 16 * l) * K + (k0 + kk)];
        }
        {
            int pp = tid & 63, kb = tid >> 6;
#pragma unroll
            for (int l = 0; l < 4; l++)
                Xs[kb + 4 * l][pp] = Xb[(size_t)(k0 + kb + 4 * l) * HW + (p0 + pp)];
        }
        __syncthreads();
#pragma unroll
        for (int kk = 0; kk < 16; kk++) {
            float a0 = Ws[kk][ty * 4 + 0];
            float a1 = Ws[kk][ty * 4 + 1];
            float a2 = Ws[kk][ty * 4 + 2];
            float a3 = Ws[kk][ty * 4 + 3];
            float4 bv = *(const float4*)&Xs[kk][tx * 4];
            acc[0][0] += a0 * bv.x; acc[0][1] += a0 * bv.y; acc[0][2] += a0 * bv.z; acc[0][3] += a0 * bv.w;
            acc[1][0] += a1 * bv.x; acc[1][1] += a1 * bv.y; acc[1][2] += a1 * bv.z; acc[1][3] += a1 * bv.w;
            acc[2][0] += a2 * bv.x; acc[2][1] += a2 * bv.y; acc[2][2] += a2 * bv.z; acc[2][3] += a2 * bv.w;
            acc[3][0] += a3 * bv.x; acc[3][1] += a3 * bv.y; acc[3][2] += a3 * bv.z; acc[3][3] += a3 * bv.w;
        }
        __syncthreads();
    }
#pragma unroll
    for (int i = 0; i < 4; i++) {
        int o = o0 + ty * 4 + i;
        float s  = gam[o] * rsqrtf(var[o] + EPS);
        float sh = beta[o] - mean[o] * s;
        float bi = bias[o];
        size_t base = (size_t)b * O * HW + (size_t)o * HW + p0 + tx * 4;
#pragma unroll
        for (int j = 0; j < 4; j++) {
            float v = fmaxf((acc[i][j] + bi) * s + sh, 0.f);
            if (resid) v += resid[base + j];
            Y[base + j] = v;
        }
    }
}

// ---------------- maxpool 3x3 s2 p1 ----------------
__global__ void maxpool_kernel(const float* __restrict__ X, float* __restrict__ Y)
{
    int idx = blockIdx.x * 256 + threadIdx.x;
    if (idx >= 8 * 128 * 1024) return;
    int q = idx & 31, p = (idx >> 5) & 31, c = (idx >> 10) & 127, b = idx >> 17;
    const float* Xp = X + ((size_t)(b * 128 + c)) * 4096;
    int r0 = 2 * p - 1, c0 = 2 * q - 1;
    float m = -CUDART_INF_F;
#pragma unroll
    for (int dr = 0; dr < 3; dr++) {
        int r = r0 + dr;
        if (r < 0 || r >= 64) continue;
#pragma unroll
        for (int dc = 0; dc < 3; dc++) {
            int cc = c0 + dc;
            if (cc < 0 || cc >= 64) continue;
            m = fmaxf(m, Xp[r * 64 + cc]);
        }
    }
    Y[idx] = m;
}

// ---------------- transpose + bf16 split kernels ----------------
__global__ void transpose_x2_kernel(const float* __restrict__ kv,
                                    __nv_bfloat16* __restrict__ oh, __nv_bfloat16* __restrict__ ol)
{
    __shared__ float t[32][33];
    int b = blockIdx.z;
    int j0 = blockIdx.x * 32, c0 = blockIdx.y * 32;
    int tx = threadIdx.x, ty = threadIdx.y;
    const float* src = kv + (size_t)b * 131072;
#pragma unroll
    for (int k = 0; k < 4; k++)
        t[ty + 8 * k][tx] = src[(size_t)(c0 + ty + 8 * k) * 1024 + j0 + tx];
    __syncthreads();
#pragma unroll
    for (int k = 0; k < 4; k++) {
        float v = t[tx][ty + 8 * k];
        __nv_bfloat16 h = __float2bfloat16(v);
        __nv_bfloat16 l = __float2bfloat16(v - __bfloat162float(h));
        size_t o = (size_t)b * 131072 + (size_t)(j0 + ty + 8 * k) * 128 + c0 + tx;
        oh[o] = h; ol[o] = l;
    }
}
__global__ void transpose_x3_kernel(const float* __restrict__ kv,
                                    __nv_bfloat16* __restrict__ oh, __nv_bfloat16* __restrict__ ol)
{
    __shared__ float t[32][33];
    int b = blockIdx.z;
    int j0 = blockIdx.x * 32, c0 = blockIdx.y * 32;
    int tx = threadIdx.x, ty = threadIdx.y;
    const float* src = kv + (size_t)b * 131072;
#pragma unroll
    for (int k = 0; k < 4; k++)
        t[ty + 8 * k][tx] = src[(size_t)(j0 + ty + 8 * k) * 128 + c0 + tx];
    __syncthreads();
#pragma unroll
    for (int k = 0; k < 4; k++) {
        float v = t[tx][ty + 8 * k];
        __nv_bfloat16 h = __float2bfloat16(v);
        __nv_bfloat16 l = __float2bfloat16(v - __bfloat162float(h));
        size_t o = (size_t)b * 131072 + (size_t)(c0 + ty + 8 * k) * 1024 + j0 + tx;
        oh[o] = h; ol[o] = l;
    }
}

// ---------------- mma.sync attention ----------------
// 256 thr, 8 warps; warp w owns rows w*16..w*16+15 of the 128-row query tile.
// smem: 4 bf16 tiles [128][PITCH], PITCH=136 -> b-frag LDS conflict-free.
#define PITCH 136
#define TILE_B (128 * PITCH * 2)                 // 34816 bytes
#define ATTN_SMEM (4 * TILE_B)                   // 139264

__global__ __launch_bounds__(256) void attn_mma_kernel(
    const float* __restrict__ x1,
    const __nv_bfloat16* __restrict__ x2h, const __nv_bfloat16* __restrict__ x2l,
    const __nv_bfloat16* __restrict__ x3h, const __nv_bfloat16* __restrict__ x3l,
    float* __restrict__ out)
{
    extern __shared__ __nv_bfloat16 smb[];
    __nv_bfloat16* B1H = smb;                    // x2t chunk [j][c]
    __nv_bfloat16* B1L = smb + 128 * PITCH;
    __nv_bfloat16* B2H = smb + 2 * 128 * PITCH;  // x3t chunk [c][j]
    __nv_bfloat16* B2L = smb + 3 * 128 * PITCH;

    const int tid  = threadIdx.x;
    const int w    = tid >> 5;
    const int lane = tid & 31;
    const int grp  = lane >> 2;      // 0..7
    const int tig  = lane & 3;       // 0..3
    const int b    = blockIdx.y;
    const int i0   = blockIdx.x * 128;
    const int r0   = w * 16 + grp;   // local row (and r0+8)

    // ---- A (X1 tile) fragments, persistent: 8 ktiles x 4 regs, hi+lo ----
    uint32_t ahi[8][4], alo[8][4];
    {
        const float* a0p = x1 + (size_t)b * 524288 + (size_t)(i0 + r0) * 128;
        const float* a1p = a0p + 8 * 128;
#pragma unroll
        for (int kt = 0; kt < 8; kt++) {
            float2 e00 = *(const float2*)(a0p + kt * 16 + 2 * tig);
            float2 e01 = *(const float2*)(a0p + kt * 16 + 2 * tig + 8);
            float2 e10 = *(const float2*)(a1p + kt * 16 + 2 * tig);
            float2 e11 = *(const float2*)(a1p + kt * 16 + 2 * tig + 8);
            split2(e00.x, e00.y, ahi[kt][0], alo[kt][0]);
            split2(e10.x, e10.y, ahi[kt][1], alo[kt][1]);
            split2(e01.x, e01.y, ahi[kt][2], alo[kt][2]);
            split2(e11.x, e11.y, ahi[kt][3], alo[kt][3]);
        }
    }

    const __nv_bfloat16* X2Hb = x2h + (size_t)b * 131072;
    const __nv_bfloat16* X2Lb = x2l + (size_t)b * 131072;
    const __nv_bfloat16* X3Hb = x3h + (size_t)b * 131072;
    const __nv_bfloat16* X3Lb = x3l + (size_t)b * 131072;

    float o[16][4];
#pragma unroll
    for (int nt = 0; nt < 16; nt++)
#pragma unroll
        for (int q = 0; q < 4; q++) o[nt][q] = 0.f;
    float m0 = -CUDART_INF_F, m1 = -CUDART_INF_F, l0 = 0.f, l1 = 0.f;

    for (int ch = 0; ch < 8; ch++) {
        const int j0 = ch * 128;
        __syncthreads();   // everyone done with previous chunk's tiles
        // fill B1 (x2t rows j0..j0+127, 128 c each) and B2 (x3t rows c, cols j0..)
        {
            const uint4* s1h = (const uint4*)(X2Hb + (size_t)j0 * 128);
            const uint4* s1l = (const uint4*)(X2Lb + (size_t)j0 * 128);
#pragma unroll
            for (int k = 0; k < 8; k++) {
                int n = tid + k * 256;       // 2048 uint4
                int r = n >> 4, p = n & 15;
                *(uint4*)(B1H + r * PITCH + p * 8) = s1h[n];
                *(uint4*)(B1L + r * PITCH + p * 8) = s1l[n];
            }
#pragma unroll
            for (int k = 0; k < 8; k++) {
                int n = tid + k * 256;
                int r = n >> 4, p = n & 15;
                *(uint4*)(B2H + r * PITCH + p * 8) = *(const uint4*)(X3Hb + (size_t)r * 1024 + j0 + p * 8);
                *(uint4*)(B2L + r * PITCH + p * 8) = *(const uint4*)(X3Lb + (size_t)r * 1024 + j0 + p * 8);
            }
        }
        __syncthreads();

        // ---- gemm1: S[16 x 128] = A x B1  (3-product bf16 split) ----
        float s[16][4];
#pragma unroll
        for (int nt = 0; nt < 16; nt++)
#pragma unroll
            for (int q = 0; q < 4; q++) s[nt][q] = 0.f;

#pragma unroll
        for (int kt = 0; kt < 8; kt++) {
#pragma unroll
            for (int nt = 0; nt < 16; nt++) {
                const __nv_bfloat16* colh = B1H + (nt * 8 + grp) * PITCH + kt * 16 + 2 * tig;
                const __nv_bfloat16* coll = B1L + (nt * 8 + grp) * PITCH + kt * 16 + 2 * tig;
                uint32_t bh0 = *(const uint32_t*)colh;
                uint32_t bh1 = *(const uint32_t*)(colh + 8);
                uint32_t bl0 = *(const uint32_t*)coll;
                uint32_t bl1 = *(const uint32_t*)(coll + 8);
                mma_bf16(s[nt][0], s[nt][1], s[nt][2], s[nt][3],
                         ahi[kt][0], ahi[kt][1], ahi[kt][2], ahi[kt][3], bh0, bh1);
                mma_bf16(s[nt][0], s[nt][1], s[nt][2], s[nt][3],
                         ahi[kt][0], ahi[kt][1], ahi[kt][2], ahi[kt][3], bl0, bl1);
                mma_bf16(s[nt][0], s[nt][1], s[nt][2], s[nt][3],
                         alo[kt][0], alo[kt][1], alo[kt][2], alo[kt][3], bh0, bh1);
            }
        }

        // ---- online softmax (rows r0, r0+8; quad = lanes sharing grp) ----
        float mx0 = s[0][0], mx1 = s[0][2];
#pragma unroll
        for (int nt = 0; nt < 16; nt++) {
            mx0 = fmaxf(mx0, fmaxf(s[nt][0], s[nt][1]));
            mx1 = fmaxf(mx1, fmaxf(s[nt][2], s[nt][3]));
        }
        mx0 = fmaxf(mx0, __shfl_xor_sync(0xffffffffu, mx0, 1));
        mx0 = fmaxf(mx0, __shfl_xor_sync(0xffffffffu, mx0, 2));
        mx1 = fmaxf(mx1, __shfl_xor_sync(0xffffffffu, mx1, 1));
        mx1 = fmaxf(mx1, __shfl_xor_sync(0xffffffffu, mx1, 2));
        float n0 = fmaxf(m0, mx0), n1 = fmaxf(m1, mx1);
        float f0 = __expf(m0 - n0), f1 = __expf(m1 - n1);
        m0 = n0; m1 = n1;
        float ps0 = 0.f, ps1 = 0.f;
#pragma unroll
        for (int nt = 0; nt < 16; nt++) {
            s[nt][0] = __expf(s[nt][0] - n0);
            s[nt][1] = __expf(s[nt][1] - n0);
            s[nt][2] = __expf(s[nt][2] - n1);
            s[nt][3] = __expf(s[nt][3] - n1);
            ps0 += s[nt][0] + s[nt][1];
            ps1 += s[nt][2] + s[nt][3];
        }
        ps0 += __shfl_xor_sync(0xffffffffu, ps0, 1);
        ps0 += __shfl_xor_sync(0xffffffffu, ps0, 2);
        ps1 += __shfl_xor_sync(0xffffffffu, ps1, 1);
        ps1 += __shfl_xor_sync(0xffffffffu, ps1, 2);
        l0 = l0 * f0 + ps0;
        l1 = l1 * f1 + ps1;
#pragma unroll
        for (int nt = 0; nt < 16; nt++) {
            o[nt][0] *= f0; o[nt][1] *= f0;
            o[nt][2] *= f1; o[nt][3] *= f1;
        }

        // ---- pack P into A-fragments (k = j dimension) ----
        uint32_t phi[8][4], plo[8][4];
#pragma unroll
        for (int kt = 0; kt < 8; kt++) {
            split2(s[2 * kt][0],     s[2 * kt][1],     phi[kt][0], plo[kt][0]);
            split2(s[2 * kt][2],     s[2 * kt][3],     phi[kt][1], plo[kt][1]);
            split2(s[2 * kt + 1][0], s[2 * kt + 1][1], phi[kt][2], plo[kt][2]);
            split2(s[2 * kt + 1][2], s[2 * kt + 1][3], phi[kt][3], plo[kt][3]);
        }

        // ---- gemm2: O += P x B2 ----
#pragma unroll
        for (int kt = 0; kt < 8; kt++) {
#pragma unroll
            for (int nt = 0; nt < 16; nt++) {
                const __nv_bfloat16* colh = B2H + (nt * 8 + grp) * PITCH + kt * 16 + 2 * tig;
                const __nv_bfloat16* coll = B2L + (nt * 8 + grp) * PITCH + kt * 16 + 2 * tig;
                uint32_t bh0 = *(const uint32_t*)colh;
                uint32_t bh1 = *(const uint32_t*)(colh + 8);
                uint32_t bl0 = *(const uint32_t*)coll;
                uint32_t bl1 = *(const uint32_t*)(coll + 8);
                mma_bf16(o[nt][0], o[nt][1], o[nt][2], o[nt][3],
                         phi[kt][0], phi[kt][1], phi[kt][2], phi[kt][3], bh0, bh1);
                mma_bf16(o[nt][0], o[nt][1], o[nt][2], o[nt][3],
                         phi[kt][0], phi[kt][1], phi[kt][2], phi[kt][3], bl0, bl1);
                mma_bf16(o[nt][0], o[nt][1], o[nt][2], o[nt][3],
                         plo[kt][0], plo[kt][1], plo[kt][2], plo[kt][3], bh0, bh1);
            }
        }
    }

    // ---- write out ----
    float inv0 = 1.0f / l0, inv1 = 1.0f / l1;
    float* og0 = out + (size_t)b * 524288 + (size_t)(i0 + r0) * 128;
    float* og1 = og0 + 8 * 128;
#pragma unroll
    for (int nt = 0; nt < 16; nt++) {
        *(float2*)(og0 + nt * 8 + 2 * tig) = make_float2(o[nt][0] * inv0, o[nt][1] * inv0);
        *(float2*)(og1 + nt * 8 + 2 * tig) = make_float2(o[nt][2] * inv1, o[nt][3] * inv1);
    }
}

// ---------------- launcher ----------------
extern "C" void kernel_launch(void* const* d_in, const int* in_sizes, int n_in,
                              void* d_out, int out_size)
{
    const float* a       = (const float*)d_in[0];
    const float* conv1_w = (const float*)d_in[1];
    const float* conv1_b = (const float*)d_in[2];
    const float* bn1_g   = (const float*)d_in[3];
    const float* bn1_b   = (const float*)d_in[4];
    const float* bn1_m   = (const float*)d_in[5];
    const float* bn1_v   = (const float*)d_in[6];
    const float* conv2_w = (const float*)d_in[7];
    const float* conv2_b = (const float*)d_in[8];
    const float* bn2_g   = (const float*)d_in[9];
    const float* bn2_b   = (const float*)d_in[10];
    const float* bn2_m   = (const float*)d_in[11];
    const float* bn2_v   = (const float*)d_in[12];
    const float* conv3_w = (const float*)d_in[13];
    const float* conv3_b = (const float*)d_in[14];
    const float* bn3_g   = (const float*)d_in[15];
    const float* bn3_b   = (const float*)d_in[16];
    const float* bn3_m   = (const float*)d_in[17];
    const float* bn3_v   = (const float*)d_in[18];
    float* out = (float*)d_out;

    float *p_x1, *p_y2, *p_x23, *p_attn;
    __nv_bfloat16 *p_x2h, *p_x2l, *p_x3h, *p_x3l;
    cudaGetSymbolAddress((void**)&p_x1,   g_x1);
    cudaGetSymbolAddress((void**)&p_y2,   g_y2);
    cudaGetSymbolAddress((void**)&p_x23,  g_x23);
    cudaGetSymbolAddress((void**)&p_attn, g_attn);
    cudaGetSymbolAddress((void**)&p_x2h,  g_x2t_hi);
    cudaGetSymbolAddress((void**)&p_x2l,  g_x2t_lo);
    cudaGetSymbolAddress((void**)&p_x3h,  g_x3t_hi);
    cudaGetSymbolAddress((void**)&p_x3l,  g_x3t_lo);

    cudaFuncSetAttribute(attn_mma_kernel, cudaFuncAttributeMaxDynamicSharedMemorySize, ATTN_SMEM);

    const int HW = 4096;
    dim3 blk(256);

    conv_bn_relu_kernel<<<dim3(HW / 64, 2, 8), blk>>>(
        a, conv1_w, conv1_b, bn1_g, bn1_b, bn1_m, bn1_v, nullptr, p_x1, 256, 128, HW);
    conv_bn_relu_kernel<<<dim3(HW / 64, 2, 8), blk>>>(
        a, conv2_w, conv2_b, bn2_g, bn2_b, bn2_m, bn2_v, nullptr, p_y2, 256, 128, HW);
    maxpool_kernel<<<(8 * 128 * 1024) / 256, blk>>>(p_y2, p_x23);

    transpose_x2_kernel<<<dim3(32, 4, 8), dim3(32, 8)>>>(p_x23, p_x2h, p_x2l);
    transpose_x3_kernel<<<dim3(32, 4, 8), dim3(32, 8)>>>(p_x23, p_x3h, p_x3l);

    attn_mma_kernel<<<dim3(32, 8), blk, ATTN_SMEM>>>(
        p_x1, p_x2h, p_x2l, p_x3h, p_x3l, p_attn);

    conv_bn_relu_kernel<<<dim3(HW / 64, 4, 8), blk>>>(
        p_attn, conv3_w, conv3_b, bn3_g, bn3_b, bn3_m, bn3_v, a, out, 128, 256, HW);
}